// round 2
// baseline (speedup 1.0000x reference)
#include <cuda_runtime.h>
#include <math.h>

// Round 1: identical to round 0 — previous bench died in the GB300 broker
// (container failed twice) before the kernel ever compiled or ran. Re-bench.

// ---------------------------------------------------------------------------
// Problem constants (fixed by setup_inputs)
// ---------------------------------------------------------------------------
#define EMBED   1280
#define HEADS   16
#define HDIM    80
#define S_TOTAL 4096
#define NSEG    4
#define SEG_LEN 1024
#define QKV_F   (3 * EMBED)   // 3840

// ---------------------------------------------------------------------------
// Scratch (device globals -- allocation inside kernel_launch is forbidden)
// ---------------------------------------------------------------------------
__device__ float g_qkv[(size_t)S_TOTAL * QKV_F];               // 62.9 MB
__device__ float g_Q[(size_t)HEADS * S_TOTAL * HDIM];          // 21 MB, [h][s][d]
__device__ float g_K[(size_t)HEADS * S_TOTAL * HDIM];          // 21 MB, [h][s][d]
__device__ float g_Vt[(size_t)HEADS * HDIM * S_TOTAL];         // 21 MB, [h][d][s]
__device__ float g_scores[(size_t)NSEG * HEADS * SEG_LEN * SEG_LEN]; // 256 MB
__device__ float g_ctx[(size_t)S_TOTAL * EMBED];               // 21 MB

// ---------------------------------------------------------------------------
// Generic batched SGEMM:  C = alpha * (A @ B^T) + bias
//   A: [M,K] row-major (lda), B: [N,K] row-major (ldb), C: [M,N] (ldc)
//   Batch z decodes as (seg = z / nh, h = z % nh); per-batch offsets applied.
//   Requires M % 128 == 0, K % 8 == 0. N may be arbitrary (guarded).
// 128x128 tile, BK=8, 256 threads, 8x8 micro-tile per thread.
// ---------------------------------------------------------------------------
#define BM 128
#define BN 128
#define BK 8

__global__ __launch_bounds__(256, 2)
void sgemm_abt(const float* __restrict__ A, const float* __restrict__ B,
               const float* __restrict__ bias, float* __restrict__ C,
               int M, int N, int K, int lda, int ldb, int ldc,
               long oAs, long oAh, long oBs, long oBh, long oCs, long oCh,
               int nh, float alpha)
{
    __shared__ float As[BK][BM + 4];
    __shared__ float Bs[BK][BN + 4];

    const int z   = blockIdx.z;
    const int seg = z / nh;
    const int h   = z % nh;
    A += oAs * seg + oAh * h;
    B += oBs * seg + oBh * h;
    C += oCs * seg + oCh * h;

    const int brow = blockIdx.y * BM;
    const int bcol = blockIdx.x * BN;

    const int tid   = threadIdx.x;       // 0..255
    const int arow  = tid >> 1;          // 0..127
    const int acol4 = (tid & 1) * 4;     // 0 or 4
    const int tx = tid % 16;
    const int ty = tid / 16;

    float acc[8][8];
#pragma unroll
    for (int i = 0; i < 8; i++)
#pragma unroll
        for (int j = 0; j < 8; j++) acc[i][j] = 0.f;

    for (int k0 = 0; k0 < K; k0 += BK) {
        // --- load A tile (rows always in-bounds: M % 128 == 0) ---
        float4 av = *(const float4*)(A + (long)(brow + arow) * lda + (k0 + acol4));
        As[acol4 + 0][arow] = av.x;
        As[acol4 + 1][arow] = av.y;
        As[acol4 + 2][arow] = av.z;
        As[acol4 + 3][arow] = av.w;

        // --- load B tile (guard N) ---
        const int bn = bcol + arow;
        float4 bv = make_float4(0.f, 0.f, 0.f, 0.f);
        if (bn < N)
            bv = *(const float4*)(B + (long)bn * ldb + (k0 + acol4));
        Bs[acol4 + 0][arow] = bv.x;
        Bs[acol4 + 1][arow] = bv.y;
        Bs[acol4 + 2][arow] = bv.z;
        Bs[acol4 + 3][arow] = bv.w;

        __syncthreads();

#pragma unroll
        for (int kk = 0; kk < BK; kk++) {
            float ra[8], rb[8];
            *(float4*)&ra[0] = *(const float4*)&As[kk][ty * 4];
            *(float4*)&ra[4] = *(const float4*)&As[kk][64 + ty * 4];
            *(float4*)&rb[0] = *(const float4*)&Bs[kk][tx * 4];
            *(float4*)&rb[4] = *(const float4*)&Bs[kk][64 + tx * 4];
#pragma unroll
            for (int i = 0; i < 8; i++)
#pragma unroll
                for (int j = 0; j < 8; j++)
                    acc[i][j] += ra[i] * rb[j];
        }
        __syncthreads();
    }

    // --- epilogue ---
#pragma unroll
    for (int i = 0; i < 8; i++) {
        const int m = brow + ((i < 4) ? (ty * 4 + i) : (64 + ty * 4 + (i - 4)));
        float* crow = C + (long)m * ldc;
#pragma unroll
        for (int j = 0; j < 8; j++) {
            const int n = bcol + ((j < 4) ? (tx * 4 + j) : (64 + tx * 4 + (j - 4)));
            if (n < N) {
                float v = alpha * acc[i][j];
                if (bias) v += bias[n];
                crow[n] = v;
            }
        }
    }
}

// ---------------------------------------------------------------------------
// Rotary embedding on q,k + relayout q,k -> [h][s][d], v -> [h][d][s]
// ---------------------------------------------------------------------------
__global__ void rotary_relayout(const float* __restrict__ qkv,
                                const float* __restrict__ rope,
                                float* __restrict__ Q, float* __restrict__ K,
                                float* __restrict__ Vt)
{
    const int s = blockIdx.x;
    const float* row = qkv + (long)s * QKV_F;

    for (int e = threadIdx.x; e < EMBED; e += blockDim.x) {
        const int h = e / HDIM;
        const int d = e % HDIM;
        const float f = rope[s * (HDIM / 2) + ((d < HDIM / 2) ? d : d - HDIM / 2)];
        float sn, cs;
        sincosf(f, &sn, &cs);

        const float qv = row[e];
        const float kv = row[EMBED + e];
        const float qp = (d < HDIM / 2) ? -row[e + HDIM / 2] : row[e - HDIM / 2];
        const float kp = (d < HDIM / 2) ? -row[EMBED + e + HDIM / 2]
                                        :  row[EMBED + e - HDIM / 2];

        const long o = ((long)h * S_TOTAL + s) * HDIM + d;
        Q[o] = qv * cs + qp * sn;
        K[o] = kv * cs + kp * sn;
        Vt[((long)h * HDIM + d) * S_TOTAL + s] = row[2 * EMBED + e];
    }
}

// ---------------------------------------------------------------------------
// Row softmax over SEG_LEN=1024 columns; one warp per row.
// ---------------------------------------------------------------------------
__global__ void softmax_rows(float* __restrict__ S)
{
    const long row  = (long)blockIdx.x * 8 + (threadIdx.x >> 5);
    const int  lane = threadIdx.x & 31;
    float* p = S + row * SEG_LEN;

    float v[32];
    float mx = -INFINITY;
#pragma unroll
    for (int i = 0; i < 32; i++) {
        v[i] = p[lane + i * 32];
        mx = fmaxf(mx, v[i]);
    }
#pragma unroll
    for (int o = 16; o; o >>= 1) mx = fmaxf(mx, __shfl_xor_sync(0xffffffffu, mx, o));

    float sum = 0.f;
#pragma unroll
    for (int i = 0; i < 32; i++) {
        v[i] = __expf(v[i] - mx);
        sum += v[i];
    }
#pragma unroll
    for (int o = 16; o; o >>= 1) sum += __shfl_xor_sync(0xffffffffu, sum, o);

    const float r = 1.f / sum;
#pragma unroll
    for (int i = 0; i < 32; i++) p[lane + i * 32] = v[i] * r;
}

// ---------------------------------------------------------------------------
// Launch helper
// ---------------------------------------------------------------------------
static void launch_sgemm(const float* A, const float* B, const float* bias,
                         float* C, int M, int N, int K,
                         int lda, int ldb, int ldc,
                         long oAs, long oAh, long oBs, long oBh,
                         long oCs, long oCh,
                         int nbatch, int nh, float alpha)
{
    dim3 grid((N + BN - 1) / BN, (M + BM - 1) / BM, nbatch);
    sgemm_abt<<<grid, 256>>>(A, B, bias, C, M, N, K, lda, ldb, ldc,
                             oAs, oAh, oBs, oBh, oCs, oCh, nh, alpha);
}

// ---------------------------------------------------------------------------
// Entry point
// ---------------------------------------------------------------------------
extern "C" void kernel_launch(void* const* d_in, const int* in_sizes, int n_in,
                              void* d_out, int out_size)
{
    const float* x      = (const float*)d_in[0]; // [4096,1,1280]
    const float* qkv_w  = (const float*)d_in[1]; // [3840,1280]
    const float* qkv_b  = (const float*)d_in[2]; // [3840]
    const float* proj_w = (const float*)d_in[3]; // [1280,1280]
    const float* proj_b = (const float*)d_in[4]; // [1280]
    const float* rope   = (const float*)d_in[5]; // [4096,40]
    float* out = (float*)d_out;                  // [4096,1,1280]

    float *qkv, *Q, *K, *Vt, *scores, *ctx;
    cudaGetSymbolAddress((void**)&qkv,    g_qkv);
    cudaGetSymbolAddress((void**)&Q,      g_Q);
    cudaGetSymbolAddress((void**)&K,      g_K);
    cudaGetSymbolAddress((void**)&Vt,     g_Vt);
    cudaGetSymbolAddress((void**)&scores, g_scores);
    cudaGetSymbolAddress((void**)&ctx,    g_ctx);

    // 1) QKV GEMM: qkv[4096,3840] = x @ qkv_w^T + qkv_b
    launch_sgemm(x, qkv_w, qkv_b, qkv,
                 S_TOTAL, QKV_F, EMBED, EMBED, EMBED, QKV_F,
                 0, 0, 0, 0, 0, 0, 1, 1, 1.0f);

    // 2) rotary + relayout
    rotary_relayout<<<S_TOTAL, 256>>>(qkv, rope, Q, K, Vt);

    // 3) scores[seg,h,q,k] = scale * Q . K   (batched over 64 (seg,h))
    const float scale = 0.11180339887498949f; // 1/sqrt(80)
    launch_sgemm(Q, K, nullptr, scores,
                 SEG_LEN, SEG_LEN, HDIM, HDIM, HDIM, SEG_LEN,
                 (long)SEG_LEN * HDIM, (long)S_TOTAL * HDIM,      // A seg/head
                 (long)SEG_LEN * HDIM, (long)S_TOTAL * HDIM,      // B seg/head
                 (long)HEADS * SEG_LEN * SEG_LEN, (long)SEG_LEN * SEG_LEN, // C
                 NSEG * HEADS, HEADS, scale);

    // 4) softmax over k
    softmax_rows<<<(NSEG * HEADS * SEG_LEN) / 8, 256>>>(scores);

    // 5) ctx[s, h*80+d] = P @ V  (B = Vt[h][d][s], A@B^T form)
    launch_sgemm(scores, Vt, nullptr, ctx,
                 SEG_LEN, HDIM, SEG_LEN, SEG_LEN, S_TOTAL, EMBED,
                 (long)HEADS * SEG_LEN * SEG_LEN, (long)SEG_LEN * SEG_LEN, // A
                 (long)SEG_LEN, (long)HDIM * S_TOTAL,                      // B
                 (long)SEG_LEN * EMBED, (long)HDIM,                        // C
                 NSEG * HEADS, HEADS, 1.0f);

    // 6) out = ctx @ proj_w^T + proj_b
    launch_sgemm(ctx, proj_w, proj_b, out,
                 S_TOTAL, EMBED, EMBED, EMBED, EMBED, EMBED,
                 0, 0, 0, 0, 0, 0, 1, 1, 1.0f);
}

// round 4
// speedup vs baseline: 1.5975x; 1.5975x over previous
#include <cuda_runtime.h>
#include <cuda_bf16.h>
#include <stdint.h>
#include <stddef.h>
#include <math.h>

// Round 3: identical logic to round 2; fixes missing <stdint.h> (uint32_t
// undefined -> 14 compile errors). bf16x3 error-compensated tensor-core GEMM.

// ---------------------------------------------------------------------------
// Problem constants
// ---------------------------------------------------------------------------
#define EMBED   1280
#define HEADS   16
#define HDIM    80
#define S_TOTAL 4096
#define NSEG    4
#define SEG_LEN 1024
#define QKV_F   (3 * EMBED)   // 3840

// ---------------------------------------------------------------------------
// Scratch
// ---------------------------------------------------------------------------
__device__ float g_qkv[(size_t)S_TOTAL * QKV_F];
__device__ float g_Q[(size_t)HEADS * S_TOTAL * HDIM];
__device__ float g_K[(size_t)HEADS * S_TOTAL * HDIM];
__device__ float g_Vt[(size_t)HEADS * HDIM * S_TOTAL];
__device__ float g_scores[(size_t)NSEG * HEADS * SEG_LEN * SEG_LEN];
__device__ float g_ctx[(size_t)S_TOTAL * EMBED];

// ---------------------------------------------------------------------------
// bf16 helpers
// ---------------------------------------------------------------------------
__device__ __forceinline__ void split2(float x0, float x1,
                                       uint32_t& hi, uint32_t& lo)
{
    __nv_bfloat16 h0 = __float2bfloat16(x0);
    __nv_bfloat16 h1 = __float2bfloat16(x1);
    float r0 = x0 - __bfloat162float(h0);
    float r1 = x1 - __bfloat162float(h1);
    __nv_bfloat162 hh;  hh.x = h0;  hh.y = h1;               // .x = low 16 bits
    __nv_bfloat162 ll;  ll.x = __float2bfloat16(r0);  ll.y = __float2bfloat16(r1);
    hi = *reinterpret_cast<uint32_t*>(&hh);
    lo = *reinterpret_cast<uint32_t*>(&ll);
}

__device__ __forceinline__ void mma16816(float* c, const uint32_t* a,
                                         uint32_t b0, uint32_t b1)
{
    asm volatile(
        "mma.sync.aligned.m16n8k16.row.col.f32.bf16.bf16.f32 "
        "{%0,%1,%2,%3}, {%4,%5,%6,%7}, {%8,%9}, {%0,%1,%2,%3};"
        : "+f"(c[0]), "+f"(c[1]), "+f"(c[2]), "+f"(c[3])
        : "r"(a[0]), "r"(a[1]), "r"(a[2]), "r"(a[3]), "r"(b0), "r"(b1));
}

// ---------------------------------------------------------------------------
// Tensor-core batched GEMM:  C = alpha * (A @ B^T) + bias
//   A: [M,K] row-major, B: [N,K] row-major, C: [M,N]
//   M % 128 == 0, K % 16 == 0. N guarded.
// Block 128x128xBK16, 256 threads (8 warps, 4x2), warp tile 32x64.
// ---------------------------------------------------------------------------
#define BM 128
#define BN 128
#define BK 16
#define BKP 12   // padded row stride in uint32 (8 used + 4 pad) -> conflict-free frags

__global__ __launch_bounds__(256)
void gemm_bf16x3(const float* __restrict__ A, const float* __restrict__ B,
                 const float* __restrict__ bias, float* __restrict__ C,
                 int M, int N, int K, int lda, int ldb, int ldc,
                 long oAs, long oAh, long oBs, long oBh, long oCs, long oCh,
                 int nh, float alpha)
{
    __shared__ uint32_t AsH[BM][BKP], AsL[BM][BKP];
    __shared__ uint32_t BsH[BN][BKP], BsL[BN][BKP];

    const int z   = blockIdx.z;
    const int seg = z / nh;
    const int h   = z % nh;
    A += oAs * seg + oAh * h;
    B += oBs * seg + oBh * h;
    C += oCs * seg + oCh * h;

    const int brow = blockIdx.y * BM;
    const int bcol = blockIdx.x * BN;

    const int tid  = threadIdx.x;
    const int warp = tid >> 5;
    const int lane = tid & 31;
    const int wm = (warp >> 1) * 32;   // warp m-offset inside tile (0,32,64,96)
    const int wn = (warp & 1) * 64;    // warp n-offset (0,64)
    const int lg  = lane >> 2;         // 0..7
    const int lq  = lane & 3;          // 0..3

    // Load-stage indices: thread covers row (tid>>1), 8 consecutive k at (tid&1)*8
    const int lrow = tid >> 1;
    const int lcol = (tid & 1) * 8;
    const int lcp  = (tid & 1) * 4;    // u32 pair column base

    float acc[2][8][4];
#pragma unroll
    for (int i = 0; i < 2; i++)
#pragma unroll
        for (int j = 0; j < 8; j++)
#pragma unroll
            for (int q = 0; q < 4; q++) acc[i][j][q] = 0.f;

    for (int k0 = 0; k0 < K; k0 += BK) {
        // ---- A tile: rows always in-bounds ----
        {
            const float* src = A + (long)(brow + lrow) * lda + (k0 + lcol);
            float4 v0 = *(const float4*)(src);
            float4 v1 = *(const float4*)(src + 4);
            float xv[8] = {v0.x, v0.y, v0.z, v0.w, v1.x, v1.y, v1.z, v1.w};
#pragma unroll
            for (int j = 0; j < 4; j++) {
                uint32_t hi, lo;
                split2(xv[2 * j], xv[2 * j + 1], hi, lo);
                AsH[lrow][lcp + j] = hi;
                AsL[lrow][lcp + j] = lo;
            }
        }
        // ---- B tile (guard N) ----
        {
            const int bn = bcol + lrow;
            float4 v0 = make_float4(0.f, 0.f, 0.f, 0.f), v1 = v0;
            if (bn < N) {
                const float* src = B + (long)bn * ldb + (k0 + lcol);
                v0 = *(const float4*)(src);
                v1 = *(const float4*)(src + 4);
            }
            float xv[8] = {v0.x, v0.y, v0.z, v0.w, v1.x, v1.y, v1.z, v1.w};
#pragma unroll
            for (int j = 0; j < 4; j++) {
                uint32_t hi, lo;
                split2(xv[2 * j], xv[2 * j + 1], hi, lo);
                BsH[lrow][lcp + j] = hi;
                BsL[lrow][lcp + j] = lo;
            }
        }
        __syncthreads();

        // ---- A fragments for both m-tiles (hi and lo) ----
        uint32_t aH[2][4], aL[2][4];
#pragma unroll
        for (int mt = 0; mt < 2; mt++) {
            const int r = wm + mt * 16 + lg;
            aH[mt][0] = AsH[r][lq];       aH[mt][1] = AsH[r + 8][lq];
            aH[mt][2] = AsH[r][lq + 4];   aH[mt][3] = AsH[r + 8][lq + 4];
            aL[mt][0] = AsL[r][lq];       aL[mt][1] = AsL[r + 8][lq];
            aL[mt][2] = AsL[r][lq + 4];   aL[mt][3] = AsL[r + 8][lq + 4];
        }

        // ---- sweep n-tiles ----
#pragma unroll
        for (int nt = 0; nt < 8; nt++) {
            const int bn = wn + nt * 8 + lg;
            uint32_t bH0 = BsH[bn][lq], bH1 = BsH[bn][lq + 4];
            uint32_t bL0 = BsL[bn][lq], bL1 = BsL[bn][lq + 4];
#pragma unroll
            for (int mt = 0; mt < 2; mt++) {
                mma16816(acc[mt][nt], aH[mt], bH0, bH1);  // hi*hi
                mma16816(acc[mt][nt], aH[mt], bL0, bL1);  // hi*lo
                mma16816(acc[mt][nt], aL[mt], bH0, bH1);  // lo*hi
            }
        }
        __syncthreads();
    }

    // ---- epilogue ----
#pragma unroll
    for (int mt = 0; mt < 2; mt++) {
        const int r0 = brow + wm + mt * 16 + lg;
#pragma unroll
        for (int nt = 0; nt < 8; nt++) {
            const int c0 = bcol + wn + nt * 8 + lq * 2;
            float* p0 = C + (long)r0 * ldc;
            float* p1 = C + (long)(r0 + 8) * ldc;
            const float b0 = bias ? bias[min(c0, N - 1)] : 0.f;
            const float b1 = bias ? bias[min(c0 + 1, N - 1)] : 0.f;
            if (c0 < N) {
                p0[c0] = alpha * acc[mt][nt][0] + b0;
                p1[c0] = alpha * acc[mt][nt][2] + b0;
            }
            if (c0 + 1 < N) {
                p0[c0 + 1] = alpha * acc[mt][nt][1] + b1;
                p1[c0 + 1] = alpha * acc[mt][nt][3] + b1;
            }
        }
    }
}

// ---------------------------------------------------------------------------
// Rotary embedding on q,k + relayout q,k -> [h][s][d], v -> [h][d][s]
// ---------------------------------------------------------------------------
__global__ void rotary_relayout(const float* __restrict__ qkv,
                                const float* __restrict__ rope,
                                float* __restrict__ Q, float* __restrict__ K,
                                float* __restrict__ Vt)
{
    const int s = blockIdx.x;
    const float* row = qkv + (long)s * QKV_F;

    for (int e = threadIdx.x; e < EMBED; e += blockDim.x) {
        const int h = e / HDIM;
        const int d = e % HDIM;
        const float f = rope[s * (HDIM / 2) + ((d < HDIM / 2) ? d : d - HDIM / 2)];
        float sn, cs;
        sincosf(f, &sn, &cs);

        const float qv = row[e];
        const float kv = row[EMBED + e];
        const float qp = (d < HDIM / 2) ? -row[e + HDIM / 2] : row[e - HDIM / 2];
        const float kp = (d < HDIM / 2) ? -row[EMBED + e + HDIM / 2]
                                        :  row[EMBED + e - HDIM / 2];

        const long o = ((long)h * S_TOTAL + s) * HDIM + d;
        Q[o] = qv * cs + qp * sn;
        K[o] = kv * cs + kp * sn;
        Vt[((long)h * HDIM + d) * S_TOTAL + s] = row[2 * EMBED + e];
    }
}

// ---------------------------------------------------------------------------
// Row softmax over SEG_LEN=1024 columns; one warp per row.
// ---------------------------------------------------------------------------
__global__ void softmax_rows(float* __restrict__ S)
{
    const long row  = (long)blockIdx.x * 8 + (threadIdx.x >> 5);
    const int  lane = threadIdx.x & 31;
    float* p = S + row * SEG_LEN;

    float v[32];
    float mx = -INFINITY;
#pragma unroll
    for (int i = 0; i < 32; i++) {
        v[i] = p[lane + i * 32];
        mx = fmaxf(mx, v[i]);
    }
#pragma unroll
    for (int o = 16; o; o >>= 1) mx = fmaxf(mx, __shfl_xor_sync(0xffffffffu, mx, o));

    float sum = 0.f;
#pragma unroll
    for (int i = 0; i < 32; i++) {
        v[i] = __expf(v[i] - mx);
        sum += v[i];
    }
#pragma unroll
    for (int o = 16; o; o >>= 1) sum += __shfl_xor_sync(0xffffffffu, sum, o);

    const float r = 1.f / sum;
#pragma unroll
    for (int i = 0; i < 32; i++) p[lane + i * 32] = v[i] * r;
}

// ---------------------------------------------------------------------------
// Launch helper
// ---------------------------------------------------------------------------
static void launch_gemm(const float* A, const float* B, const float* bias,
                        float* C, int M, int N, int K,
                        int lda, int ldb, int ldc,
                        long oAs, long oAh, long oBs, long oBh,
                        long oCs, long oCh,
                        int nbatch, int nh, float alpha)
{
    dim3 grid((N + BN - 1) / BN, (M + BM - 1) / BM, nbatch);
    gemm_bf16x3<<<grid, 256>>>(A, B, bias, C, M, N, K, lda, ldb, ldc,
                               oAs, oAh, oBs, oBh, oCs, oCh, nh, alpha);
}

// ---------------------------------------------------------------------------
// Entry point
// ---------------------------------------------------------------------------
extern "C" void kernel_launch(void* const* d_in, const int* in_sizes, int n_in,
                              void* d_out, int out_size)
{
    const float* x      = (const float*)d_in[0]; // [4096,1,1280]
    const float* qkv_w  = (const float*)d_in[1]; // [3840,1280]
    const float* qkv_b  = (const float*)d_in[2]; // [3840]
    const float* proj_w = (const float*)d_in[3]; // [1280,1280]
    const float* proj_b = (const float*)d_in[4]; // [1280]
    const float* rope   = (const float*)d_in[5]; // [4096,40]
    float* out = (float*)d_out;                  // [4096,1,1280]

    float *qkv, *Q, *K, *Vt, *scores, *ctx;
    cudaGetSymbolAddress((void**)&qkv,    g_qkv);
    cudaGetSymbolAddress((void**)&Q,      g_Q);
    cudaGetSymbolAddress((void**)&K,      g_K);
    cudaGetSymbolAddress((void**)&Vt,     g_Vt);
    cudaGetSymbolAddress((void**)&scores, g_scores);
    cudaGetSymbolAddress((void**)&ctx,    g_ctx);

    // 1) QKV GEMM: qkv[4096,3840] = x @ qkv_w^T + qkv_b
    launch_gemm(x, qkv_w, qkv_b, qkv,
                S_TOTAL, QKV_F, EMBED, EMBED, EMBED, QKV_F,
                0, 0, 0, 0, 0, 0, 1, 1, 1.0f);

    // 2) rotary + relayout
    rotary_relayout<<<S_TOTAL, 256>>>(qkv, rope, Q, K, Vt);

    // 3) scores[seg,h,q,k] = scale * Q . K   (batched over 64 (seg,h))
    const float scale = 0.11180339887498949f; // 1/sqrt(80)
    launch_gemm(Q, K, nullptr, scores,
                SEG_LEN, SEG_LEN, HDIM, HDIM, HDIM, SEG_LEN,
                (long)SEG_LEN * HDIM, (long)S_TOTAL * HDIM,
                (long)SEG_LEN * HDIM, (long)S_TOTAL * HDIM,
                (long)HEADS * SEG_LEN * SEG_LEN, (long)SEG_LEN * SEG_LEN,
                NSEG * HEADS, HEADS, scale);

    // 4) softmax over k
    softmax_rows<<<(NSEG * HEADS * SEG_LEN) / 8, 256>>>(scores);

    // 5) ctx[s, h*80+d] = P @ V  (B = Vt[h][d][s])
    launch_gemm(scores, Vt, nullptr, ctx,
                SEG_LEN, HDIM, SEG_LEN, SEG_LEN, S_TOTAL, EMBED,
                (long)HEADS * SEG_LEN * SEG_LEN, (long)SEG_LEN * SEG_LEN,
                (long)SEG_LEN, (long)HDIM * S_TOTAL,
                (long)SEG_LEN * EMBED, (long)HDIM,
                NSEG * HEADS, HEADS, 1.0f);

    // 6) out = ctx @ proj_w^T + proj_b
    launch_gemm(ctx, proj_w, proj_b, out,
                S_TOTAL, EMBED, EMBED, EMBED, EMBED, EMBED,
                0, 0, 0, 0, 0, 0, 1, 1, 1.0f);
}

// round 5
// speedup vs baseline: 1.9305x; 1.2085x over previous
#include <cuda_runtime.h>
#include <cuda_bf16.h>
#include <stdint.h>
#include <stddef.h>
#include <math.h>

// Round 5: GEMM operands pre-split to bf16 hi/lo in GLOBAL memory (conversion
// out of the inner loop), cp.async double-buffered BK=32 pipeline, pure
// LDS+HMMA mainloop. Fragment/epilogue mappings identical to round-4 (passed).

// ---------------------------------------------------------------------------
// Problem constants
// ---------------------------------------------------------------------------
#define EMBED   1280
#define HEADS   16
#define HDIM    80
#define HDIMP   96            // HDIM padded to multiple of BK (zero tail)
#define S_TOTAL 4096
#define NSEG    4
#define SEG_LEN 1024
#define QKV_F   (3 * EMBED)   // 3840

// ---------------------------------------------------------------------------
// Scratch (device globals; zero-initialized at module load -> K-pad stays 0)
// ---------------------------------------------------------------------------
__device__ float    g_qkv[(size_t)S_TOTAL * QKV_F];                    // fp32
__device__ float    g_scores[(size_t)NSEG * HEADS * SEG_LEN * SEG_LEN];
__device__ float    g_ctx[(size_t)S_TOTAL * EMBED];

__device__ uint16_t g_xh[(size_t)S_TOTAL * EMBED],   g_xl[(size_t)S_TOTAL * EMBED];
__device__ uint16_t g_wh[(size_t)QKV_F * EMBED],     g_wl[(size_t)QKV_F * EMBED];
__device__ uint16_t g_pwh[(size_t)EMBED * EMBED],    g_pwl[(size_t)EMBED * EMBED];
__device__ uint16_t g_Qh[(size_t)HEADS * S_TOTAL * HDIMP], g_Ql[(size_t)HEADS * S_TOTAL * HDIMP];
__device__ uint16_t g_Kh[(size_t)HEADS * S_TOTAL * HDIMP], g_Kl[(size_t)HEADS * S_TOTAL * HDIMP];
__device__ uint16_t g_Vth[(size_t)HEADS * HDIM * S_TOTAL], g_Vtl[(size_t)HEADS * HDIM * S_TOTAL];
__device__ uint16_t g_Ph[(size_t)NSEG * HEADS * SEG_LEN * SEG_LEN];
__device__ uint16_t g_Pl[(size_t)NSEG * HEADS * SEG_LEN * SEG_LEN];
__device__ uint16_t g_ch[(size_t)S_TOTAL * EMBED],   g_cl[(size_t)S_TOTAL * EMBED];

// ---------------------------------------------------------------------------
// helpers
// ---------------------------------------------------------------------------
__device__ __forceinline__ uint16_t bf_bits(__nv_bfloat16 h)
{
    return *reinterpret_cast<uint16_t*>(&h);
}

__device__ __forceinline__ void split1(float x, uint16_t& hi, uint16_t& lo)
{
    __nv_bfloat16 h = __float2bfloat16(x);
    float r = x - __bfloat162float(h);
    hi = bf_bits(h);
    lo = bf_bits(__float2bfloat16(r));
}

__device__ __forceinline__ void mma16816(float* c, const uint32_t* a,
                                         uint32_t b0, uint32_t b1)
{
    asm volatile(
        "mma.sync.aligned.m16n8k16.row.col.f32.bf16.bf16.f32 "
        "{%0,%1,%2,%3}, {%4,%5,%6,%7}, {%8,%9}, {%0,%1,%2,%3};"
        : "+f"(c[0]), "+f"(c[1]), "+f"(c[2]), "+f"(c[3])
        : "r"(a[0]), "r"(a[1]), "r"(a[2]), "r"(a[3]), "r"(b0), "r"(b1));
}

__device__ __forceinline__ void cp_async16(uint32_t dst_smem, const void* src)
{
    asm volatile("cp.async.cg.shared.global [%0], [%1], 16;"
                 :: "r"(dst_smem), "l"(src));
}
__device__ __forceinline__ void cp_async16z(uint32_t dst_smem, const void* src, int src_bytes)
{
    asm volatile("cp.async.cg.shared.global [%0], [%1], 16, %2;"
                 :: "r"(dst_smem), "l"(src), "r"(src_bytes));
}
__device__ __forceinline__ void cp_commit()
{
    asm volatile("cp.async.commit_group;");
}
template <int N>
__device__ __forceinline__ void cp_wait()
{
    asm volatile("cp.async.wait_group %0;" :: "n"(N));
}

// ---------------------------------------------------------------------------
// Tensor-core batched GEMM:  C = alpha * (A @ B^T) + bias
//   A,B given as bf16 hi/lo pairs (row-major, leading dims in elements).
//   M % 128 == 0 (grid), K % 32 == 0, N guarded (ragged rows zero-filled).
// Block 128x128, BK=32, 256 threads (8 warps 4x2), 2-stage cp.async pipeline.
// ---------------------------------------------------------------------------
#define BM 128
#define BN 128
#define BK 32
#define BKP 20                    // u32 per smem row (16 used + 4 pad)
#define SUB (128 * BKP)           // u32 per sub-array
#define STG (4 * SUB)             // u32 per stage
// sub-array offsets (u32): AH 0, AL SUB, BH 2*SUB, BL 3*SUB
#define SMEM_BYTES (2 * STG * 4)  // 81920

__global__ __launch_bounds__(256, 2)
void gemm_bf16x3(const uint16_t* __restrict__ Ah, const uint16_t* __restrict__ Al,
                 const uint16_t* __restrict__ Bh, const uint16_t* __restrict__ Bl,
                 const float* __restrict__ bias, float* __restrict__ C,
                 int N, int K, int lda, int ldb, int ldc,
                 long oAs, long oAh_, long oBs, long oBh_, long oCs, long oCh_,
                 int nh, float alpha)
{
    extern __shared__ uint32_t sm[];

    const int z   = blockIdx.z;
    const int seg = z / nh;
    const int h   = z % nh;
    Ah += oAs * seg + oAh_ * h;  Al += oAs * seg + oAh_ * h;
    Bh += oBs * seg + oBh_ * h;  Bl += oBs * seg + oBh_ * h;
    C  += oCs * seg + oCh_ * h;

    const int brow = blockIdx.y * BM;
    const int bcol = blockIdx.x * BN;

    const int tid  = threadIdx.x;
    const int warp = tid >> 5;
    const int lane = tid & 31;
    const int wm = (warp >> 1) * 32;
    const int wn = (warp & 1) * 64;
    const int lg = lane >> 2;
    const int lq = lane & 3;

    const uint32_t smem_base = (uint32_t)__cvta_generic_to_shared(sm);

    // loader indices: thread covers row tid>>2 (+64), 16B chunk q = tid&3
    const int lrow = tid >> 2;
    const int lq4  = (tid & 3) * 4;        // u32 col of chunk
    const int lk8  = (tid & 3) * 8;        // bf16 col of chunk

    float acc[2][8][4];
#pragma unroll
    for (int i = 0; i < 2; i++)
#pragma unroll
        for (int j = 0; j < 8; j++)
#pragma unroll
            for (int q = 0; q < 4; q++) acc[i][j][q] = 0.f;

    const int nit = K / BK;

    // ---- stage loader (cp.async) ----
    auto load_stage = [&](int stage, int k0) {
        const uint32_t sb = smem_base + (uint32_t)stage * STG * 4;
#pragma unroll
        for (int r2 = 0; r2 < 2; r2++) {
            const int row = lrow + r2 * 64;
            const uint32_t doff = (uint32_t)(row * BKP + lq4) * 4;
            // A rows always in-bounds
            cp_async16(sb + 0 * SUB * 4 + doff,
                       Ah + (long)(brow + row) * lda + k0 + lk8);
            cp_async16(sb + 1 * SUB * 4 + doff,
                       Al + (long)(brow + row) * lda + k0 + lk8);
            // B rows guarded (zero-fill out-of-range)
            const int bn  = bcol + row;
            const int ok  = (bn < N) ? 16 : 0;
            const int bno = (bn < N) ? bn : 0;
            cp_async16z(sb + 2 * SUB * 4 + doff,
                        Bh + (long)bno * ldb + k0 + lk8, ok);
            cp_async16z(sb + 3 * SUB * 4 + doff,
                        Bl + (long)bno * ldb + k0 + lk8, ok);
        }
    };

    load_stage(0, 0);
    cp_commit();

    for (int it = 0; it < nit; it++) {
        if (it + 1 < nit) {
            load_stage((it + 1) & 1, (it + 1) * BK);
            cp_commit();
            cp_wait<1>();
        } else {
            cp_wait<0>();
        }
        __syncthreads();

        const uint32_t* sAH = sm + (it & 1) * STG;
        const uint32_t* sAL = sAH + SUB;
        const uint32_t* sBH = sAH + 2 * SUB;
        const uint32_t* sBL = sAH + 3 * SUB;

#pragma unroll
        for (int kc = 0; kc < 2; kc++) {
            const int kb = kc * 8;
            uint32_t aH[2][4], aL[2][4];
#pragma unroll
            for (int mt = 0; mt < 2; mt++) {
                const int r = wm + mt * 16 + lg;
                aH[mt][0] = sAH[r * BKP + kb + lq];
                aH[mt][1] = sAH[(r + 8) * BKP + kb + lq];
                aH[mt][2] = sAH[r * BKP + kb + lq + 4];
                aH[mt][3] = sAH[(r + 8) * BKP + kb + lq + 4];
                aL[mt][0] = sAL[r * BKP + kb + lq];
                aL[mt][1] = sAL[(r + 8) * BKP + kb + lq];
                aL[mt][2] = sAL[r * BKP + kb + lq + 4];
                aL[mt][3] = sAL[(r + 8) * BKP + kb + lq + 4];
            }
#pragma unroll
            for (int nt = 0; nt < 8; nt++) {
                const int bn = wn + nt * 8 + lg;
                const uint32_t bH0 = sBH[bn * BKP + kb + lq];
                const uint32_t bH1 = sBH[bn * BKP + kb + lq + 4];
                const uint32_t bL0 = sBL[bn * BKP + kb + lq];
                const uint32_t bL1 = sBL[bn * BKP + kb + lq + 4];
#pragma unroll
                for (int mt = 0; mt < 2; mt++) {
                    mma16816(acc[mt][nt], aH[mt], bH0, bH1);  // hi*hi
                    mma16816(acc[mt][nt], aH[mt], bL0, bL1);  // hi*lo
                    mma16816(acc[mt][nt], aL[mt], bH0, bH1);  // lo*hi
                }
            }
        }
        __syncthreads();
    }

    // ---- epilogue (same mapping as round 4) ----
#pragma unroll
    for (int mt = 0; mt < 2; mt++) {
        const int r0 = brow + wm + mt * 16 + lg;
#pragma unroll
        for (int nt = 0; nt < 8; nt++) {
            const int c0 = bcol + wn + nt * 8 + lq * 2;
            float* p0 = C + (long)r0 * ldc;
            float* p1 = C + (long)(r0 + 8) * ldc;
            const float b0 = bias ? bias[min(c0, N - 1)] : 0.f;
            const float b1 = bias ? bias[min(c0 + 1, N - 1)] : 0.f;
            if (c0 < N) {
                p0[c0] = alpha * acc[mt][nt][0] + b0;
                p1[c0] = alpha * acc[mt][nt][2] + b0;
            }
            if (c0 + 1 < N) {
                p0[c0 + 1] = alpha * acc[mt][nt][1] + b1;
                p1[c0 + 1] = alpha * acc[mt][nt][3] + b1;
            }
        }
    }
}

// ---------------------------------------------------------------------------
// fp32 -> bf16 hi/lo split (elementwise)
// ---------------------------------------------------------------------------
__global__ void split_f32(const float* __restrict__ in,
                          uint16_t* __restrict__ hi, uint16_t* __restrict__ lo,
                          long n)
{
    const long i = (long)blockIdx.x * blockDim.x + threadIdx.x;
    if (i < n) {
        uint16_t h, l;
        split1(in[i], h, l);
        hi[i] = h;
        lo[i] = l;
    }
}

// ---------------------------------------------------------------------------
// Rotary + relayout, writing bf16 hi/lo:
//   Q,K -> [h][s][HDIMP] (tail 80..95 untouched = zero), Vt -> [h][d][s]
// ---------------------------------------------------------------------------
__global__ void rotary_relayout(const float* __restrict__ qkv,
                                const float* __restrict__ rope,
                                uint16_t* __restrict__ Qh, uint16_t* __restrict__ Ql,
                                uint16_t* __restrict__ Kh, uint16_t* __restrict__ Kl,
                                uint16_t* __restrict__ Vth, uint16_t* __restrict__ Vtl)
{
    const int s = blockIdx.x;
    const float* row = qkv + (long)s * QKV_F;

    for (int e = threadIdx.x; e < EMBED; e += blockDim.x) {
        const int h = e / HDIM;
        const int d = e % HDIM;
        const float f = rope[s * (HDIM / 2) + ((d < HDIM / 2) ? d : d - HDIM / 2)];
        float sn, cs;
        sincosf(f, &sn, &cs);

        const float qv = row[e];
        const float kv = row[EMBED + e];
        const float qp = (d < HDIM / 2) ? -row[e + HDIM / 2] : row[e - HDIM / 2];
        const float kp = (d < HDIM / 2) ? -row[EMBED + e + HDIM / 2]
                                        :  row[EMBED + e - HDIM / 2];

        const float qr = qv * cs + qp * sn;
        const float kr = kv * cs + kp * sn;

        const long oq = ((long)h * S_TOTAL + s) * HDIMP + d;
        uint16_t hh, ll;
        split1(qr, hh, ll);  Qh[oq] = hh;  Ql[oq] = ll;
        split1(kr, hh, ll);  Kh[oq] = hh;  Kl[oq] = ll;

        const long ov = ((long)h * HDIM + d) * S_TOTAL + s;
        split1(row[2 * EMBED + e], hh, ll);  Vth[ov] = hh;  Vtl[ov] = ll;
    }
}

// ---------------------------------------------------------------------------
// Row softmax over 1024 cols; one warp per row; outputs bf16 hi/lo probs.
// ---------------------------------------------------------------------------
__global__ void softmax_rows(const float* __restrict__ S,
                             uint16_t* __restrict__ Ph, uint16_t* __restrict__ Pl)
{
    const long row  = (long)blockIdx.x * 8 + (threadIdx.x >> 5);
    const int  lane = threadIdx.x & 31;
    const float* p = S + row * SEG_LEN;

    float v[32];
    float mx = -INFINITY;
#pragma unroll
    for (int i = 0; i < 32; i++) {
        v[i] = p[lane + i * 32];
        mx = fmaxf(mx, v[i]);
    }
#pragma unroll
    for (int o = 16; o; o >>= 1) mx = fmaxf(mx, __shfl_xor_sync(0xffffffffu, mx, o));

    float sum = 0.f;
#pragma unroll
    for (int i = 0; i < 32; i++) {
        v[i] = __expf(v[i] - mx);
        sum += v[i];
    }
#pragma unroll
    for (int o = 16; o; o >>= 1) sum += __shfl_xor_sync(0xffffffffu, sum, o);

    const float r = 1.f / sum;
    uint16_t* ph = Ph + row * SEG_LEN;
    uint16_t* pl = Pl + row * SEG_LEN;
#pragma unroll
    for (int i = 0; i < 32; i++) {
        uint16_t hh, ll;
        split1(v[i] * r, hh, ll);
        ph[lane + i * 32] = hh;
        pl[lane + i * 32] = ll;
    }
}

// ---------------------------------------------------------------------------
// Launch helper
// ---------------------------------------------------------------------------
static void launch_gemm(const uint16_t* Ah, const uint16_t* Al,
                        const uint16_t* Bh, const uint16_t* Bl,
                        const float* bias, float* C,
                        int M, int N, int K, int lda, int ldb, int ldc,
                        long oAs, long oAh_, long oBs, long oBh_,
                        long oCs, long oCh_, int nbatch, int nh, float alpha)
{
    dim3 grid((N + BN - 1) / BN, M / BM, nbatch);
    gemm_bf16x3<<<grid, 256, SMEM_BYTES>>>(Ah, Al, Bh, Bl, bias, C,
                                           N, K, lda, ldb, ldc,
                                           oAs, oAh_, oBs, oBh_, oCs, oCh_,
                                           nh, alpha);
}

// ---------------------------------------------------------------------------
// Entry point
// ---------------------------------------------------------------------------
extern "C" void kernel_launch(void* const* d_in, const int* in_sizes, int n_in,
                              void* d_out, int out_size)
{
    const float* x      = (const float*)d_in[0];
    const float* qkv_w  = (const float*)d_in[1];
    const float* qkv_b  = (const float*)d_in[2];
    const float* proj_w = (const float*)d_in[3];
    const float* proj_b = (const float*)d_in[4];
    const float* rope   = (const float*)d_in[5];
    float* out = (float*)d_out;

    cudaFuncSetAttribute(gemm_bf16x3,
                         cudaFuncAttributeMaxDynamicSharedMemorySize, SMEM_BYTES);

    float *qkv, *scores, *ctx;
    uint16_t *xh, *xl, *wh, *wl, *pwh, *pwl;
    uint16_t *Qh, *Ql, *Kh, *Kl, *Vth, *Vtl, *Ph, *Pl, *ch, *cl;
    cudaGetSymbolAddress((void**)&qkv,    g_qkv);
    cudaGetSymbolAddress((void**)&scores, g_scores);
    cudaGetSymbolAddress((void**)&ctx,    g_ctx);
    cudaGetSymbolAddress((void**)&xh,  g_xh);   cudaGetSymbolAddress((void**)&xl,  g_xl);
    cudaGetSymbolAddress((void**)&wh,  g_wh);   cudaGetSymbolAddress((void**)&wl,  g_wl);
    cudaGetSymbolAddress((void**)&pwh, g_pwh);  cudaGetSymbolAddress((void**)&pwl, g_pwl);
    cudaGetSymbolAddress((void**)&Qh,  g_Qh);   cudaGetSymbolAddress((void**)&Ql,  g_Ql);
    cudaGetSymbolAddress((void**)&Kh,  g_Kh);   cudaGetSymbolAddress((void**)&Kl,  g_Kl);
    cudaGetSymbolAddress((void**)&Vth, g_Vth);  cudaGetSymbolAddress((void**)&Vtl, g_Vtl);
    cudaGetSymbolAddress((void**)&Ph,  g_Ph);   cudaGetSymbolAddress((void**)&Pl,  g_Pl);
    cudaGetSymbolAddress((void**)&ch,  g_ch);   cudaGetSymbolAddress((void**)&cl,  g_cl);

    // 0) split inputs/weights to bf16 hi/lo
    {
        long n1 = (long)S_TOTAL * EMBED;
        long n2 = (long)QKV_F * EMBED;
        long n3 = (long)EMBED * EMBED;
        split_f32<<<(unsigned)((n1 + 255) / 256), 256>>>(x, xh, xl, n1);
        split_f32<<<(unsigned)((n2 + 255) / 256), 256>>>(qkv_w, wh, wl, n2);
        split_f32<<<(unsigned)((n3 + 255) / 256), 256>>>(proj_w, pwh, pwl, n3);
    }

    // 1) QKV GEMM: qkv[4096,3840] = x @ qkv_w^T + qkv_b
    launch_gemm(xh, xl, wh, wl, qkv_b, qkv,
                S_TOTAL, QKV_F, EMBED, EMBED, EMBED, QKV_F,
                0, 0, 0, 0, 0, 0, 1, 1, 1.0f);

    // 2) rotary + relayout -> bf16 hi/lo Q,K (K-dim padded to 96), Vt
    rotary_relayout<<<S_TOTAL, 256>>>(qkv, rope, Qh, Ql, Kh, Kl, Vth, Vtl);

    // 3) scores = scale * Q @ K^T   (64 batches of 1024x1024x96)
    const float scale = 0.11180339887498949f; // 1/sqrt(80)
    launch_gemm(Qh, Ql, Kh, Kl, nullptr, scores,
                SEG_LEN, SEG_LEN, HDIMP, HDIMP, HDIMP, SEG_LEN,
                (long)SEG_LEN * HDIMP, (long)S_TOTAL * HDIMP,
                (long)SEG_LEN * HDIMP, (long)S_TOTAL * HDIMP,
                (long)HEADS * SEG_LEN * SEG_LEN, (long)SEG_LEN * SEG_LEN,
                NSEG * HEADS, HEADS, scale);

    // 4) softmax -> bf16 hi/lo probs
    softmax_rows<<<(NSEG * HEADS * SEG_LEN) / 8, 256>>>(scores, Ph, Pl);

    // 5) ctx = P @ Vt^T   (N=80 ragged, zero-filled)
    launch_gemm(Ph, Pl, Vth, Vtl, nullptr, ctx,
                SEG_LEN, HDIM, SEG_LEN, SEG_LEN, S_TOTAL, EMBED,
                (long)HEADS * SEG_LEN * SEG_LEN, (long)SEG_LEN * SEG_LEN,
                (long)SEG_LEN, (long)HDIM * S_TOTAL,
                (long)SEG_LEN * EMBED, (long)HDIM,
                NSEG * HEADS, HEADS, 1.0f);

    // 6) split ctx, then out = ctx @ proj_w^T + proj_b
    {
        long n = (long)S_TOTAL * EMBED;
        split_f32<<<(unsigned)((n + 255) / 256), 256>>>(ctx, ch, cl, n);
    }
    launch_gemm(ch, cl, pwh, pwl, proj_b, out,
                S_TOTAL, EMBED, EMBED, EMBED, EMBED, EMBED,
                0, 0, 0, 0, 0, 0, 1, 1, 1.0f);
}